// round 2
// baseline (speedup 1.0000x reference)
#include <cuda_runtime.h>

#define NHX 64
#define NHY 64
#define NU  512
#define NV  512
#define LCH 16
#define NPLANES 6

#define CAPN 1000000
#define TILE_SHIFT 3                     // 8x8 grid cells per uv tile
#define UV_TILES 64                      // 512 >> 3
#define NBUCKETS (8 * UV_TILES * UV_TILES)   // m (8) x 64 x 64 = 32768

// Static scratch (allocation-free rule: __device__ globals)
__device__ int    g_count[NBUCKETS];
__device__ int    g_ptr[NBUCKETS];       // exclusive offsets, consumed by scatter
__device__ float4 g_rec[CAPN];           // {hx, hy, u, v} in sorted order
__device__ int    g_idx[CAPN];           // pt | (m << 24)

// ---------------- sort pipeline ----------------

__device__ __forceinline__ int bucket_of(int mi, float uu, float vv) {
    int uc = (int)(uu * (float)NU); if (uc > NU - 1) uc = NU - 1;
    int vc = (int)(vv * (float)NV); if (vc > NV - 1) vc = NV - 1;
    return (mi << 12) | ((uc >> TILE_SHIFT) << 6) | (vc >> TILE_SHIFT);
}

__global__ void zero_kernel() {
    int i = blockIdx.x * blockDim.x + threadIdx.x;
    if (i < NBUCKETS) g_count[i] = 0;
}

__global__ void hist_kernel(const int* __restrict__ m,
                            const float* __restrict__ u,
                            const float* __restrict__ v, int N) {
    int pt = blockIdx.x * blockDim.x + threadIdx.x;
    if (pt >= N) return;
    atomicAdd(&g_count[bucket_of(m[pt], u[pt], v[pt])], 1);
}

// single block, 1024 threads, 32 buckets each
__global__ void scan_kernel() {
    __shared__ int sh[1024];
    int t = threadIdx.x;
    int base = t * 32;
    int s = 0;
#pragma unroll
    for (int i = 0; i < 32; i++) s += g_count[base + i];
    sh[t] = s;
    __syncthreads();
    // Hillis-Steele inclusive scan
    for (int off = 1; off < 1024; off <<= 1) {
        int val = (t >= off) ? sh[t - off] : 0;
        __syncthreads();
        sh[t] += val;
        __syncthreads();
    }
    int ex = sh[t] - s;   // exclusive prefix of this thread's chunk
#pragma unroll
    for (int i = 0; i < 32; i++) {
        int c = g_count[base + i];
        g_ptr[base + i] = ex;
        ex += c;
    }
}

__global__ void scatter_kernel(const int* __restrict__ m,
                               const float* __restrict__ h,
                               const float* __restrict__ u,
                               const float* __restrict__ v, int N) {
    int pt = blockIdx.x * blockDim.x + threadIdx.x;
    if (pt >= N) return;
    int   mi = m[pt];
    float uu = u[pt], vv = v[pt];
    int b = bucket_of(mi, uu, vv);
    int pos = atomicAdd(&g_ptr[b], 1);
    g_rec[pos] = make_float4(h[2 * pt], h[2 * pt + 1], uu, vv);
    g_idx[pos] = pt | (mi << 24);
}

// ---------------- interpolation ----------------

__device__ __forceinline__ void axis(float ind, int I, int& i1, int& i2, float& fr) {
    if (ind == (float)I) ind = (float)(I - 1);
    i1 = (int)ind;
    fr = ind - (float)i1;
    i2 = i1 + 1;
    if (i2 == I) i2 = 0;
}

__device__ __forceinline__ float4 bilerp4(const float* __restrict__ F,
                                          int mi, int I, int J,
                                          int i1, int i2, float ir,
                                          int j1, int j2, float jr, int q) {
    int rowA = (mi * I + i1) * J;
    int rowB = (mi * I + i2) * J;
    const float4* p11 = reinterpret_cast<const float4*>(F + (size_t)(rowA + j1) * LCH) + q;
    const float4* p21 = reinterpret_cast<const float4*>(F + (size_t)(rowB + j1) * LCH) + q;
    const float4* p12 = reinterpret_cast<const float4*>(F + (size_t)(rowA + j2) * LCH) + q;
    const float4* p22 = reinterpret_cast<const float4*>(F + (size_t)(rowB + j2) * LCH) + q;
    float4 a = __ldg(p11);
    float4 b = __ldg(p21);
    float4 c = __ldg(p12);
    float4 d = __ldg(p22);
    float omi = 1.0f - ir, omj = 1.0f - jr;
    float4 out;
    out.x = (a.x * omi + b.x * ir) * omj + (c.x * omi + d.x * ir) * jr;
    out.y = (a.y * omi + b.y * ir) * omj + (c.y * omi + d.y * ir) * jr;
    out.z = (a.z * omi + b.z * ir) * omj + (c.z * omi + d.z * ir) * jr;
    out.w = (a.w * omi + b.w * ir) * omj + (c.w * omi + d.w * ir) * jr;
    return out;
}

__global__ void __launch_bounds__(256)
triplane_sorted_kernel(const float* __restrict__ Fxy,
                       const float* __restrict__ Fxu,
                       const float* __restrict__ Fxv,
                       const float* __restrict__ Fyu,
                       const float* __restrict__ Fyv,
                       const float* __restrict__ Fuv,
                       float4*      __restrict__ out,
                       int N) {
    int gid = blockIdx.x * blockDim.x + threadIdx.x;
    int p   = gid >> 2;      // sorted position
    int q   = gid & 3;
    if (p >= N) return;

    float4 rec = g_rec[p];
    int packed = g_idx[p];
    int pt = packed & 0x00FFFFFF;
    int mi = packed >> 24;

    float ind_hx = (rec.x + 1.0f) / 2.0f * (float)NHX;
    float ind_hy = (rec.y + 1.0f) / 2.0f * (float)NHY;
    float ind_u  = rec.z * (float)NU;
    float ind_v  = rec.w * (float)NV;

    int x1, x2, y1, y2, u1, u2, v1, v2;
    float xr, yr, ur, vr;
    axis(ind_hx, NHX, x1, x2, xr);
    axis(ind_hy, NHY, y1, y2, yr);
    axis(ind_u,  NU,  u1, u2, ur);
    axis(ind_v,  NV,  v1, v2, vr);

    float4* o = out + (size_t)pt * (NPLANES * (LCH / 4));

    o[0 * 4 + q] = bilerp4(Fxy, mi, NHX, NHY, x1, x2, xr, y1, y2, yr, q);
    o[1 * 4 + q] = bilerp4(Fxu, mi, NHX, NU,  x1, x2, xr, u1, u2, ur, q);
    o[2 * 4 + q] = bilerp4(Fxv, mi, NHX, NV,  x1, x2, xr, v1, v2, vr, q);
    o[3 * 4 + q] = bilerp4(Fyu, mi, NHY, NU,  y1, y2, yr, u1, u2, ur, q);
    o[4 * 4 + q] = bilerp4(Fyv, mi, NHY, NV,  y1, y2, yr, v1, v2, vr, q);
    o[5 * 4 + q] = bilerp4(Fuv, mi, NU,  NV,  u1, u2, ur, v1, v2, vr, q);
}

// Fallback (unsorted) kernel, used only if N exceeds static scratch capacity.
__global__ void __launch_bounds__(256)
triplane_direct_kernel(const int*   __restrict__ m,
                       const float* __restrict__ h,
                       const float* __restrict__ u,
                       const float* __restrict__ v,
                       const float* __restrict__ Fxy,
                       const float* __restrict__ Fxu,
                       const float* __restrict__ Fxv,
                       const float* __restrict__ Fyu,
                       const float* __restrict__ Fyv,
                       const float* __restrict__ Fuv,
                       float4*      __restrict__ out,
                       int N) {
    int gid = blockIdx.x * blockDim.x + threadIdx.x;
    int pt  = gid >> 2;
    int q   = gid & 3;
    if (pt >= N) return;

    int   mi = m[pt];
    float ind_hx = (h[2 * pt] + 1.0f) / 2.0f * (float)NHX;
    float ind_hy = (h[2 * pt + 1] + 1.0f) / 2.0f * (float)NHY;
    float ind_u  = u[pt] * (float)NU;
    float ind_v  = v[pt] * (float)NV;

    int x1, x2, y1, y2, u1, u2, v1, v2;
    float xr, yr, ur, vr;
    axis(ind_hx, NHX, x1, x2, xr);
    axis(ind_hy, NHY, y1, y2, yr);
    axis(ind_u,  NU,  u1, u2, ur);
    axis(ind_v,  NV,  v1, v2, vr);

    float4* o = out + (size_t)pt * (NPLANES * (LCH / 4));
    o[0 * 4 + q] = bilerp4(Fxy, mi, NHX, NHY, x1, x2, xr, y1, y2, yr, q);
    o[1 * 4 + q] = bilerp4(Fxu, mi, NHX, NU,  x1, x2, xr, u1, u2, ur, q);
    o[2 * 4 + q] = bilerp4(Fxv, mi, NHX, NV,  x1, x2, xr, v1, v2, vr, q);
    o[3 * 4 + q] = bilerp4(Fyu, mi, NHY, NU,  y1, y2, yr, u1, u2, ur, q);
    o[4 * 4 + q] = bilerp4(Fyv, mi, NHY, NV,  y1, y2, yr, v1, v2, vr, q);
    o[5 * 4 + q] = bilerp4(Fuv, mi, NU,  NV,  u1, u2, ur, v1, v2, vr, q);
}

extern "C" void kernel_launch(void* const* d_in, const int* in_sizes, int n_in,
                              void* d_out, int out_size) {
    // order: r, m, h, u, v, Fxy, Fxu, Fxv, Fyu, Fyv, Fuv   (r unused)
    const int*   m   = (const int*)  d_in[1];
    const float* h   = (const float*)d_in[2];
    const float* u   = (const float*)d_in[3];
    const float* v   = (const float*)d_in[4];
    const float* Fxy = (const float*)d_in[5];
    const float* Fxu = (const float*)d_in[6];
    const float* Fxv = (const float*)d_in[7];
    const float* Fyu = (const float*)d_in[8];
    const float* Fyv = (const float*)d_in[9];
    const float* Fuv = (const float*)d_in[10];

    int N = in_sizes[1];

    if (N <= CAPN) {
        int tpb = 256;
        zero_kernel<<<(NBUCKETS + tpb - 1) / tpb, tpb>>>();
        hist_kernel<<<(N + tpb - 1) / tpb, tpb>>>(m, u, v, N);
        scan_kernel<<<1, 1024>>>();
        scatter_kernel<<<(N + tpb - 1) / tpb, tpb>>>(m, h, u, v, N);

        long long tt = (long long)N * 4;
        triplane_sorted_kernel<<<(int)((tt + tpb - 1) / tpb), tpb>>>(
            Fxy, Fxu, Fxv, Fyu, Fyv, Fuv, (float4*)d_out, N);
    } else {
        long long tt = (long long)N * 4;
        int tpb = 256;
        triplane_direct_kernel<<<(int)((tt + tpb - 1) / tpb), tpb>>>(
            m, h, u, v, Fxy, Fxu, Fxv, Fyu, Fyv, Fuv, (float4*)d_out, N);
    }
}